// round 10
// baseline (speedup 1.0000x reference)
#include <cuda_runtime.h>
#include <cuda_bf16.h>
#include <cuda_fp16.h>
#include <cstdint>
#include <math.h>

// Problem constants
#define CB   2
#define CS   2048
#define CHID 2048
#define CH   8
#define CD   256
#define CM   (CB*CS)          // 4096 rows
#define CHALF (CD/2)          // 128

// ---------------- scratch (device globals; no allocation allowed) ----------
__device__ float g_q[(size_t)CM * CHID];            // (b,s,h,d)
__device__ float g_k[(size_t)CM * CD];              // (b,s,d)   KH=1
__device__ float g_v[(size_t)CM * CD];
__device__ float g_invl[(size_t)CB * CH * CS];      // 1/rowsum
__device__ float g_attn_fb[(size_t)CB * CH * CS * CS]; // fallback attn buffer

// bf16 hi/lo split buffers (exp-path operands: hs, Wq/Wk/Wv, q, k)
__device__ __nv_bfloat16 g_hs_h[(size_t)CM * CHID];   // reused later for q split
__device__ __nv_bfloat16 g_hs_l[(size_t)CM * CHID];
__device__ __nv_bfloat16 g_wq_h[(size_t)CHID * CHID];
__device__ __nv_bfloat16 g_wq_l[(size_t)CHID * CHID];
__device__ __nv_bfloat16 g_wk_h[(size_t)CD * CHID];
__device__ __nv_bfloat16 g_wk_l[(size_t)CD * CHID];
__device__ __nv_bfloat16 g_wv_h[(size_t)CD * CHID];
__device__ __nv_bfloat16 g_wv_l[(size_t)CD * CHID];
__device__ __nv_bfloat16 g_kh[(size_t)CM * CD];
__device__ __nv_bfloat16 g_kl[(size_t)CM * CD];

// fp16 buffers (linear-path operands: V^T, Wo, ctx)
__device__ __half g_vth[(size_t)CB * CD * CS];        // (b, d, s) hi
__device__ __half g_vtl[(size_t)CB * CD * CS];        // lo
__device__ __half g_wo_h[(size_t)CHID * CHID];        // Wo*64 hi
__device__ __half g_wo_l[(size_t)CHID * CHID];        // Wo*64 lo
__device__ __half g_ctxf[(size_t)CM * CHID];          // ctx fp16 (b,s,h*d)

#define g_qh g_hs_h
#define g_ql g_hs_l

// ---------------- fp32 -> bf16 hi/lo split ----------------------------------
__global__ void split_kernel(const float* __restrict__ src,
                             __nv_bfloat16* __restrict__ hi,
                             __nv_bfloat16* __restrict__ lo, int n4)
{
    int i = blockIdx.x * 256 + threadIdx.x;
    if (i >= n4) return;
    float4 v = ((const float4*)src)[i];
    __nv_bfloat16 h0 = __float2bfloat16_rn(v.x);
    __nv_bfloat16 h1 = __float2bfloat16_rn(v.y);
    __nv_bfloat16 h2 = __float2bfloat16_rn(v.z);
    __nv_bfloat16 h3 = __float2bfloat16_rn(v.w);
    __nv_bfloat16 l0 = __float2bfloat16_rn(v.x - __bfloat162float(h0));
    __nv_bfloat16 l1 = __float2bfloat16_rn(v.y - __bfloat162float(h1));
    __nv_bfloat16 l2 = __float2bfloat16_rn(v.z - __bfloat162float(h2));
    __nv_bfloat16 l3 = __float2bfloat16_rn(v.w - __bfloat162float(h3));
    __nv_bfloat162 hh0; hh0.x = h0; hh0.y = h1;
    __nv_bfloat162 hh1; hh1.x = h2; hh1.y = h3;
    __nv_bfloat162 ll0; ll0.x = l0; ll0.y = l1;
    __nv_bfloat162 ll1; ll1.x = l2; ll1.y = l3;
    ((__nv_bfloat162*)hi)[i*2]   = hh0;
    ((__nv_bfloat162*)hi)[i*2+1] = hh1;
    ((__nv_bfloat162*)lo)[i*2]   = ll0;
    ((__nv_bfloat162*)lo)[i*2+1] = ll1;
}

// ---------------- fp32 -> fp16 hi/lo split (with pre-scale) ------------------
__global__ void splitf16_kernel(const float* __restrict__ src,
                                __half* __restrict__ hi,
                                __half* __restrict__ lo, int n4, float scale)
{
    int i = blockIdx.x * 256 + threadIdx.x;
    if (i >= n4) return;
    float4 v = ((const float4*)src)[i];
    float x0 = v.x * scale, x1 = v.y * scale, x2 = v.z * scale, x3 = v.w * scale;
    __half h0 = __float2half_rn(x0);
    __half h1 = __float2half_rn(x1);
    __half h2 = __float2half_rn(x2);
    __half h3 = __float2half_rn(x3);
    __half l0 = __float2half_rn(x0 - __half2float(h0));
    __half l1 = __float2half_rn(x1 - __half2float(h1));
    __half l2 = __float2half_rn(x2 - __half2float(h2));
    __half l3 = __float2half_rn(x3 - __half2float(h3));
    __half2 hh0; hh0.x = h0; hh0.y = h1;
    __half2 hh1; hh1.x = h2; hh1.y = h3;
    __half2 ll0; ll0.x = l0; ll0.y = l1;
    __half2 ll1; ll1.x = l2; ll1.y = l3;
    ((__half2*)hi)[i*2]   = hh0;
    ((__half2*)hi)[i*2+1] = hh1;
    ((__half2*)lo)[i*2]   = ll0;
    ((__half2*)lo)[i*2+1] = ll1;
}

// ---------------- V transpose + fp16 split: (b,s,d) f32 -> (b,d,s) ----------
__global__ __launch_bounds__(256) void vsplitT_kernel()
{
    __shared__ float tile[32][33];
    int b  = blockIdx.z;
    int s0 = blockIdx.x * 32, d0 = blockIdx.y * 32;
    int tx = threadIdx.x & 31, ty = threadIdx.x >> 5;
#pragma unroll
    for (int i = 0; i < 32; i += 8)
        tile[ty + i][tx] = g_v[((size_t)(b * CS + s0 + ty + i)) * CD + d0 + tx];
    __syncthreads();
#pragma unroll
    for (int i = 0; i < 32; i += 8) {
        float v = tile[tx][ty + i];
        __half hh = __float2half_rn(v);
        size_t o = ((size_t)(b * CD + d0 + ty + i)) * CS + s0 + tx;
        g_vth[o] = hh;
        g_vtl[o] = __float2half_rn(v - __half2float(hh));
    }
}

// ---------------- mma helpers -----------------------------------------------
__device__ __forceinline__ uint32_t sptr(const void* p) {
    return (uint32_t)__cvta_generic_to_shared(p);
}

#define LDM4(d0,d1,d2,d3,addr) asm volatile( \
  "ldmatrix.sync.aligned.m8n8.x4.shared.b16 {%0,%1,%2,%3}, [%4];" \
  : "=r"(d0),"=r"(d1),"=r"(d2),"=r"(d3) : "r"(addr))

#define MMA16816(c,a,b) asm volatile( \
  "mma.sync.aligned.m16n8k16.row.col.f32.bf16.bf16.f32 " \
  "{%0,%1,%2,%3}, {%4,%5,%6,%7}, {%8,%9}, {%0,%1,%2,%3};" \
  : "+f"((c)[0]),"+f"((c)[1]),"+f"((c)[2]),"+f"((c)[3]) \
  : "r"((a)[0]),"r"((a)[1]),"r"((a)[2]),"r"((a)[3]),"r"((b)[0]),"r"((b)[1]))

#define MMAF16(c,a,b) asm volatile( \
  "mma.sync.aligned.m16n8k16.row.col.f32.f16.f16.f32 " \
  "{%0,%1,%2,%3}, {%4,%5,%6,%7}, {%8,%9}, {%0,%1,%2,%3};" \
  : "+f"((c)[0]),"+f"((c)[1]),"+f"((c)[2]),"+f"((c)[3]) \
  : "r"((a)[0]),"r"((a)[1]),"r"((a)[2]),"r"((a)[3]),"r"((b)[0]),"r"((b)[1]))

// ---------------- tensor-core GEMM (bf16 3-pass split) ----------------------
__global__ __launch_bounds__(256) void gemm_bf16x3(
    const __nv_bfloat16* __restrict__ Ah, const __nv_bfloat16* __restrict__ Al,
    const __nv_bfloat16* __restrict__ Bh, const __nv_bfloat16* __restrict__ Bl,
    const float* __restrict__ bias, float* __restrict__ C,
    int M, int N, int K)
{
    __shared__ __nv_bfloat16 sAh[128][40], sAl[128][40];
    __shared__ __nv_bfloat16 sBh[128][40], sBl[128][40];

    const int tid  = threadIdx.x;
    const int lane = tid & 31;
    const int warp = tid >> 5;
    const int wm = (warp & 1) * 64;
    const int wn = (warp >> 1) * 32;
    const int bm = blockIdx.y * 128;
    const int bn = blockIdx.x * 128;

    const int lr = tid >> 2;
    const int lc = (tid & 3) * 8;

    float acc[4][4][4];
#pragma unroll
    for (int i = 0; i < 4; i++)
#pragma unroll
        for (int j = 0; j < 4; j++)
#pragma unroll
            for (int r = 0; r < 4; r++) acc[i][j][r] = 0.f;

    const __nv_bfloat16* pAh = Ah + (size_t)(bm + lr) * K + lc;
    const __nv_bfloat16* pAl = Al + (size_t)(bm + lr) * K + lc;
    const __nv_bfloat16* pBh = Bh + (size_t)(bn + lr) * K + lc;
    const __nv_bfloat16* pBl = Bl + (size_t)(bn + lr) * K + lc;

    uint4 ra0, ra1, ra2, ra3, rb0, rb1, rb2, rb3;
    ra0 = *(const uint4*)(pAh);
    ra1 = *(const uint4*)(pAh + (size_t)64 * K);
    ra2 = *(const uint4*)(pAl);
    ra3 = *(const uint4*)(pAl + (size_t)64 * K);
    rb0 = *(const uint4*)(pBh);
    rb1 = *(const uint4*)(pBh + (size_t)64 * K);
    rb2 = *(const uint4*)(pBl);
    rb3 = *(const uint4*)(pBl + (size_t)64 * K);

    const int arow = lane & 15;
    const int acol = (lane >> 4) * 8;
    const int brow = (lane & 7) + ((lane & 16) >> 1);
    const int bcol = (lane & 8);

    int k0 = 0;
    for (;;) {
        __syncthreads();
        *(uint4*)&sAh[lr][lc]      = ra0;
        *(uint4*)&sAh[lr + 64][lc] = ra1;
        *(uint4*)&sAl[lr][lc]      = ra2;
        *(uint4*)&sAl[lr + 64][lc] = ra3;
        *(uint4*)&sBh[lr][lc]      = rb0;
        *(uint4*)&sBh[lr + 64][lc] = rb1;
        *(uint4*)&sBl[lr][lc]      = rb2;
        *(uint4*)&sBl[lr + 64][lc] = rb3;
        __syncthreads();

        k0 += 32;
        if (k0 < K) {
            ra0 = *(const uint4*)(pAh + k0);
            ra1 = *(const uint4*)(pAh + (size_t)64 * K + k0);
            ra2 = *(const uint4*)(pAl + k0);
            ra3 = *(const uint4*)(pAl + (size_t)64 * K + k0);
            rb0 = *(const uint4*)(pBh + k0);
            rb1 = *(const uint4*)(pBh + (size_t)64 * K + k0);
            rb2 = *(const uint4*)(pBl + k0);
            rb3 = *(const uint4*)(pBl + (size_t)64 * K + k0);
        }

#pragma unroll
        for (int ks = 0; ks < 2; ks++) {
            const int kb = ks * 16;
            uint32_t ah[4][4], al[4][4];
#pragma unroll
            for (int mt = 0; mt < 4; mt++) {
                uint32_t adr = sptr(&sAh[wm + mt*16 + arow][kb + acol]);
                LDM4(ah[mt][0], ah[mt][1], ah[mt][2], ah[mt][3], adr);
                adr = sptr(&sAl[wm + mt*16 + arow][kb + acol]);
                LDM4(al[mt][0], al[mt][1], al[mt][2], al[mt][3], adr);
            }
            uint32_t bh[4][2], bl[4][2];
#pragma unroll
            for (int np = 0; np < 2; np++) {
                uint32_t r0, r1, r2, r3;
                uint32_t adr = sptr(&sBh[wn + np*16 + brow][kb + bcol]);
                LDM4(r0, r1, r2, r3, adr);
                bh[np*2][0] = r0; bh[np*2][1] = r1;
                bh[np*2+1][0] = r2; bh[np*2+1][1] = r3;
                adr = sptr(&sBl[wn + np*16 + brow][kb + bcol]);
                LDM4(r0, r1, r2, r3, adr);
                bl[np*2][0] = r0; bl[np*2][1] = r1;
                bl[np*2+1][0] = r2; bl[np*2+1][1] = r3;
            }
#pragma unroll
            for (int mt = 0; mt < 4; mt++)
#pragma unroll
                for (int nt = 0; nt < 4; nt++) {
                    MMA16816(acc[mt][nt], ah[mt], bh[nt]);
                    MMA16816(acc[mt][nt], ah[mt], bl[nt]);
                    MMA16816(acc[mt][nt], al[mt], bh[nt]);
                }
        }
        if (k0 >= K) break;
    }

    const int crow = lane >> 2;
    const int ccol = (lane & 3) * 2;
#pragma unroll
    for (int mt = 0; mt < 4; mt++) {
#pragma unroll
        for (int nt = 0; nt < 4; nt++) {
            int gr = bm + wm + mt*16 + crow;
            int gc = bn + wn + nt*8 + ccol;
            float2 b2 = *(const float2*)(bias + gc);
            float2 o0 = make_float2(acc[mt][nt][0] + b2.x, acc[mt][nt][1] + b2.y);
            float2 o1 = make_float2(acc[mt][nt][2] + b2.x, acc[mt][nt][3] + b2.y);
            *(float2*)(C + (size_t)gr * N + gc)       = o0;
            *(float2*)(C + (size_t)(gr + 8) * N + gc) = o1;
        }
    }
}

// ---------------- tensor-core GEMM (fp16 2-pass: A single, B hi/lo) ---------
// C[m,n] = (sum_k A[m,k]*(Bh+Bl)[n,k]) * inv_scale + bias[n]
__global__ __launch_bounds__(256) void gemm_f16x2(
    const __half* __restrict__ A,
    const __half* __restrict__ Bh, const __half* __restrict__ Bl,
    const float* __restrict__ bias, float* __restrict__ C,
    int M, int N, int K, float inv_scale)
{
    __shared__ __half sA[128][40];
    __shared__ __half sBh[128][40], sBl[128][40];

    const int tid  = threadIdx.x;
    const int lane = tid & 31;
    const int warp = tid >> 5;
    const int wm = (warp & 1) * 64;
    const int wn = (warp >> 1) * 32;
    const int bm = blockIdx.y * 128;
    const int bn = blockIdx.x * 128;

    const int lr = tid >> 2;
    const int lc = (tid & 3) * 8;

    float acc[4][4][4];
#pragma unroll
    for (int i = 0; i < 4; i++)
#pragma unroll
        for (int j = 0; j < 4; j++)
#pragma unroll
            for (int r = 0; r < 4; r++) acc[i][j][r] = 0.f;

    const __half* pA  = A  + (size_t)(bm + lr) * K + lc;
    const __half* pBh = Bh + (size_t)(bn + lr) * K + lc;
    const __half* pBl = Bl + (size_t)(bn + lr) * K + lc;

    uint4 ra0, ra1, rb0, rb1, rb2, rb3;
    ra0 = *(const uint4*)(pA);
    ra1 = *(const uint4*)(pA + (size_t)64 * K);
    rb0 = *(const uint4*)(pBh);
    rb1 = *(const uint4*)(pBh + (size_t)64 * K);
    rb2 = *(const uint4*)(pBl);
    rb3 = *(const uint4*)(pBl + (size_t)64 * K);

    const int arow = lane & 15;
    const int acol = (lane >> 4) * 8;
    const int brow = (lane & 7) + ((lane & 16) >> 1);
    const int bcol = (lane & 8);

    int k0 = 0;
    for (;;) {
        __syncthreads();
        *(uint4*)&sA[lr][lc]       = ra0;
        *(uint4*)&sA[lr + 64][lc]  = ra1;
        *(uint4*)&sBh[lr][lc]      = rb0;
        *(uint4*)&sBh[lr + 64][lc] = rb1;
        *(uint4*)&sBl[lr][lc]      = rb2;
        *(uint4*)&sBl[lr + 64][lc] = rb3;
        __syncthreads();

        k0 += 32;
        if (k0 < K) {
            ra0 = *(const uint4*)(pA + k0);
            ra1 = *(const uint4*)(pA + (size_t)64 * K + k0);
            rb0 = *(const uint4*)(pBh + k0);
            rb1 = *(const uint4*)(pBh + (size_t)64 * K + k0);
            rb2 = *(const uint4*)(pBl + k0);
            rb3 = *(const uint4*)(pBl + (size_t)64 * K + k0);
        }

#pragma unroll
        for (int ks = 0; ks < 2; ks++) {
            const int kb = ks * 16;
            uint32_t a[4][4];
#pragma unroll
            for (int mt = 0; mt < 4; mt++) {
                uint32_t adr = sptr(&sA[wm + mt*16 + arow][kb + acol]);
                LDM4(a[mt][0], a[mt][1], a[mt][2], a[mt][3], adr);
            }
            uint32_t bh[4][2], bl[4][2];
#pragma unroll
            for (int np = 0; np < 2; np++) {
                uint32_t r0, r1, r2, r3;
                uint32_t adr = sptr(&sBh[wn + np*16 + brow][kb + bcol]);
                LDM4(r0, r1, r2, r3, adr);
                bh[np*2][0] = r0; bh[np*2][1] = r1;
                bh[np*2+1][0] = r2; bh[np*2+1][1] = r3;
                adr = sptr(&sBl[wn + np*16 + brow][kb + bcol]);
                LDM4(r0, r1, r2, r3, adr);
                bl[np*2][0] = r0; bl[np*2][1] = r1;
                bl[np*2+1][0] = r2; bl[np*2+1][1] = r3;
            }
#pragma unroll
            for (int mt = 0; mt < 4; mt++)
#pragma unroll
                for (int nt = 0; nt < 4; nt++) {
                    MMAF16(acc[mt][nt], a[mt], bh[nt]);
                    MMAF16(acc[mt][nt], a[mt], bl[nt]);
                }
        }
        if (k0 >= K) break;
    }

    const int crow = lane >> 2;
    const int ccol = (lane & 3) * 2;
#pragma unroll
    for (int mt = 0; mt < 4; mt++) {
#pragma unroll
        for (int nt = 0; nt < 4; nt++) {
            int gr = bm + wm + mt*16 + crow;
            int gc = bn + wn + nt*8 + ccol;
            float2 b2 = *(const float2*)(bias + gc);
            float2 o0 = make_float2(acc[mt][nt][0]*inv_scale + b2.x,
                                    acc[mt][nt][1]*inv_scale + b2.y);
            float2 o1 = make_float2(acc[mt][nt][2]*inv_scale + b2.x,
                                    acc[mt][nt][3]*inv_scale + b2.y);
            *(float2*)(C + (size_t)gr * N + gc)       = o0;
            *(float2*)(C + (size_t)(gr + 8) * N + gc) = o1;
        }
    }
}

// ---------------- RoPE -------------------------------------------------------
__global__ void rope_kernel(const int* __restrict__ pos)
{
    int idx = blockIdx.x * 256 + threadIdx.x;
    const int total = CB * CS * (CH + 1) * CHALF;
    if (idx >= total) return;
    int i  = idx & (CHALF - 1);
    int t  = idx >> 7;
    int hh = t % (CH + 1);
    int bs = t / (CH + 1);
    float p = (float)pos[bs];
    float inv = powf(10000.0f, -(float)i * (1.0f / 128.0f));
    float f = p * inv;
    float s, c;
    sincosf(f, &s, &c);
    float* ptr = (hh < CH) ? (g_q + ((size_t)bs * CH + hh) * CD)
                           : (g_k + (size_t)bs * CD);
    float x1 = ptr[i], x2 = ptr[i + CHALF];
    ptr[i]         = c * x1 - s * x2;
    ptr[i + CHALF] = s * x1 + c * x2;
}

// ---------------- tensor-core fused attention -------------------------------
// QK^T: bf16 3-pass (exp path). PV: fp16 2-pass (P single fp16, V hi/lo fp16).
// ctx written directly as fp16 (feeds the fp16 O-proj).
#define BQ 64
#define BK 64
#define QS 264
#define VS 72
#define ATTN2_SMEM ((2*(BQ*QS) + 2*(BK*QS) + 2*(256*VS) + (BQ*VS))*2 + (128+64)*4)

__global__ __launch_bounds__(256) void attn_mma_kernel(
    const float* __restrict__ maskp, float* __restrict__ attn)
{
    extern __shared__ __align__(16) __nv_bfloat16 smb[];
    __nv_bfloat16* sQh = smb;
    __nv_bfloat16* sQl = sQh + BQ*QS;
    __nv_bfloat16* sKh = sQl + BQ*QS;
    __nv_bfloat16* sKl = sKh + BK*QS;
    __half* sVh = (__half*)(sKl + BK*QS);
    __half* sVl = sVh + 256*VS;
    __half* sP  = sVl + 256*VS;            // single fp16 P
    float* sRS  = (float*)(sP + BQ*VS);    // [64][2] partial row sums
    float* sInv = sRS + 128;               // [64]

    const int tid  = threadIdx.x;
    const int lane = tid & 31;
    const int warp = tid >> 5;
    const int wm = warp >> 1;
    const int wn = warp & 1;
    const int qt = blockIdx.x, h = blockIdx.y, b = blockIdx.z;
    const int r0 = qt * BQ;

    const int arow = lane & 15;
    const int acol = (lane >> 4) * 8;
    const int brow = (lane & 7) + ((lane & 16) >> 1);
    const int bcol = (lane & 8);
    const int crow = lane >> 2;
    const int ccol = (lane & 3) * 2;

#pragma unroll
    for (int it = 0; it < 8; it++) {
        int e = it * 256 + tid;
        int row = e >> 5, k8 = (e & 31) * 8;
        size_t g = ((size_t)(b * CS + r0 + row) * CH + h) * CD + k8;
        *(uint4*)&sQh[row * QS + k8] = *(const uint4*)&g_qh[g];
        *(uint4*)&sQl[row * QS + k8] = *(const uint4*)&g_ql[g];
    }

    float acc_o[16][4];
#pragma unroll
    for (int i = 0; i < 16; i++)
#pragma unroll
        for (int r = 0; r < 4; r++) acc_o[i][r] = 0.f;
    float lsum0 = 0.f, lsum1 = 0.f;
    const float scale = 0.0625f;

    for (int c0 = 0; c0 < CS; c0 += BK) {
        __syncthreads();
#pragma unroll
        for (int it = 0; it < 8; it++) {
            int e = it * 256 + tid;
            int row = e >> 5, k8 = (e & 31) * 8;
            size_t g = (size_t)(b * CS + c0 + row) * CD + k8;
            *(uint4*)&sKh[row * QS + k8] = *(const uint4*)&g_kh[g];
            *(uint4*)&sKl[row * QS + k8] = *(const uint4*)&g_kl[g];
        }
#pragma unroll
        for (int it = 0; it < 8; it++) {
            int e = it * 256 + tid;
            int d = e >> 3, kq = (e & 7) * 8;
            size_t g = (size_t)(b * CD + d) * CS + c0 + kq;
            *(uint4*)&sVh[d * VS + kq] = *(const uint4*)&g_vth[g];
            *(uint4*)&sVl[d * VS + kq] = *(const uint4*)&g_vtl[g];
        }
        __syncthreads();

        // ---- QK^T (bf16 3-pass) ----
        float acc_s[4][4];
#pragma unroll
        for (int j = 0; j < 4; j++)
#pragma unroll
            for (int r = 0; r < 4; r++) acc_s[j][r] = 0.f;

#pragma unroll
        for (int kk = 0; kk < CD; kk += 16) {
            uint32_t ah[4], al[4];
            uint32_t adr = sptr(&sQh[(wm*16 + arow) * QS + kk + acol]);
            LDM4(ah[0], ah[1], ah[2], ah[3], adr);
            adr = sptr(&sQl[(wm*16 + arow) * QS + kk + acol]);
            LDM4(al[0], al[1], al[2], al[3], adr);
            uint32_t bh[4][2], bl[4][2];
#pragma unroll
            for (int np = 0; np < 2; np++) {
                uint32_t r0r, r1r, r2r, r3r;
                adr = sptr(&sKh[(wn*32 + np*16 + brow) * QS + kk + bcol]);
                LDM4(r0r, r1r, r2r, r3r, adr);
                bh[np*2][0] = r0r; bh[np*2][1] = r1r;
                bh[np*2+1][0] = r2r; bh[np*2+1][1] = r3r;
                adr = sptr(&sKl[(wn*32 + np*16 + brow) * QS + kk + bcol]);
                LDM4(r0r, r1r, r2r, r3r, adr);
                bl[np*2][0] = r0r; bl[np*2][1] = r1r;
                bl[np*2+1][0] = r2r; bl[np*2+1][1] = r3r;
            }
#pragma unroll
            for (int nt = 0; nt < 4; nt++) {
                MMA16816(acc_s[nt], ah, bh[nt]);
                MMA16816(acc_s[nt], ah, bl[nt]);
                MMA16816(acc_s[nt], al, bh[nt]);
            }
        }

        // ---- exp + attn write + stage P (single fp16) ----
        {
            int r = wm*16 + crow;
            size_t rb0 = ((size_t)(b * CH + h) * CS + r0 + r) * CS;
            size_t rb1 = rb0 + (size_t)8 * CS;
#pragma unroll
            for (int nt = 0; nt < 4; nt++) {
                int kl = wn*32 + nt*8 + ccol;
                int kg = c0 + kl;
                float m0 = maskp[b * CS + kg];
                float m1 = maskp[b * CS + kg + 1];
                float p00 = __expf(acc_s[nt][0] * scale + m0);
                float p01 = __expf(acc_s[nt][1] * scale + m1);
                float p10 = __expf(acc_s[nt][2] * scale + m0);
                float p11 = __expf(acc_s[nt][3] * scale + m1);
                lsum0 += p00 + p01;
                lsum1 += p10 + p11;
                *(float2*)&attn[rb0 + kg] = make_float2(p00, p01);
                *(float2*)&attn[rb1 + kg] = make_float2(p10, p11);
                *(__half2*)&sP[r * VS + kl]       = __floats2half2_rn(p00, p01);
                *(__half2*)&sP[(r + 8) * VS + kl] = __floats2half2_rn(p10, p11);
            }
        }
        __syncthreads();

        // ---- PV (fp16 2-pass): 16 rows x 128 d per warp ----
#pragma unroll
        for (int kc = 0; kc < 4; kc++) {
            uint32_t ph[4];
            uint32_t adr = sptr(&sP[(wm*16 + arow) * VS + kc*16 + acol]);
            LDM4(ph[0], ph[1], ph[2], ph[3], adr);
#pragma unroll
            for (int np = 0; np < 8; np++) {
                uint32_t r0r, r1r, r2r, r3r;
                uint32_t vh0[2], vh1[2], vl0[2], vl1[2];
                adr = sptr(&sVh[(wn*128 + np*16 + brow) * VS + kc*16 + bcol]);
                LDM4(r0r, r1r, r2r, r3r, adr);
                vh0[0] = r0r; vh0[1] = r1r; vh1[0] = r2r; vh1[1] = r3r;
                adr = sptr(&sVl[(wn*128 + np*16 + brow) * VS + kc*16 + bcol]);
                LDM4(r0r, r1r, r2r, r3r, adr);
                vl0[0] = r0r; vl0[1] = r1r; vl1[0] = r2r; vl1[1] = r3r;
                MMAF16(acc_o[np*2],   ph, vh0);
                MMAF16(acc_o[np*2],   ph, vl0);
                MMAF16(acc_o[np*2+1], ph, vh1);
                MMAF16(acc_o[np*2+1], ph, vl1);
            }
        }
    }

    lsum0 += __shfl_xor_sync(0xffffffff, lsum0, 1);
    lsum0 += __shfl_xor_sync(0xffffffff, lsum0, 2);
    lsum1 += __shfl_xor_sync(0xffffffff, lsum1, 1);
    lsum1 += __shfl_xor_sync(0xffffffff, lsum1, 2);
    if ((lane & 3) == 0) {
        sRS[(wm*16 + crow) * 2 + wn]     = lsum0;
        sRS[(wm*16 + crow + 8) * 2 + wn] = lsum1;
    }
    __syncthreads();
    if (tid < 64) {
        float inv = 1.0f / (sRS[tid*2] + sRS[tid*2 + 1]);
        sInv[tid] = inv;
        g_invl[((size_t)(b * CH + h)) * CS + r0 + tid] = inv;
    }
    __syncthreads();

    // normalized ctx out as fp16: (b, s, h*d)
    {
        int r = wm*16 + crow;
        float inv0 = sInv[r], inv1 = sInv[r + 8];
        size_t ob0 = ((size_t)(b * CS + r0 + r) * CH + h) * CD;
        size_t ob1 = ((size_t)(b * CS + r0 + r + 8) * CH + h) * CD;
#pragma unroll
        for (int nt = 0; nt < 16; nt++) {
            int d = wn*128 + nt*8 + ccol;
            *(__half2*)&g_ctxf[ob0 + d] =
                __floats2half2_rn(acc_o[nt][0]*inv0, acc_o[nt][1]*inv0);
            *(__half2*)&g_ctxf[ob1 + d] =
                __floats2half2_rn(acc_o[nt][2]*inv1, acc_o[nt][3]*inv1);
        }
    }
}

// ---------------- normalize attn rows by 1/l --------------------------------
__global__ void attn_scale_kernel(float* __restrict__ attn)
{
    size_t i = (size_t)blockIdx.x * 256 + threadIdx.x;
    float4* a4 = (float4*)attn;
    size_t row = i >> 9;
    float inv = g_invl[row];
    float4 v = a4[i];
    v.x *= inv; v.y *= inv; v.z *= inv; v.w *= inv;
    a4[i] = v;
}

// ---------------- launch ----------------------------------------------------
extern "C" void kernel_launch(void* const* d_in, const int* in_sizes, int n_in,
                              void* d_out, int out_size)
{
    const float* hs   = (const float*)d_in[0];
    const float* mask = (const float*)d_in[1];
    const int*   pos  = (const int*)  d_in[2];
    const float* Wq   = (const float*)d_in[3];
    const float* bq   = (const float*)d_in[4];
    const float* Wk   = (const float*)d_in[5];
    const float* bk   = (const float*)d_in[6];
    const float* Wv   = (const float*)d_in[7];
    const float* bv   = (const float*)d_in[8];
    const float* Wo   = (const float*)d_in[9];
    const float* bo   = (const float*)d_in[10];
    float* out = (float*)d_out;

    float *qp, *kp, *vp, *attnfb;
    cudaGetSymbolAddress((void**)&qp,     g_q);
    cudaGetSymbolAddress((void**)&kp,     g_k);
    cudaGetSymbolAddress((void**)&vp,     g_v);
    cudaGetSymbolAddress((void**)&attnfb, g_attn_fb);

    __nv_bfloat16 *hsh, *hsl, *wqh, *wql, *wkh, *wkl, *wvh, *wvl, *kbh, *kbl;
    __half *woh, *wol, *ctxf;
    cudaGetSymbolAddress((void**)&hsh, g_hs_h);  cudaGetSymbolAddress((void**)&hsl, g_hs_l);
    cudaGetSymbolAddress((void**)&wqh, g_wq_h);  cudaGetSymbolAddress((void**)&wql, g_wq_l);
    cudaGetSymbolAddress((void**)&wkh, g_wk_h);  cudaGetSymbolAddress((void**)&wkl, g_wk_l);
    cudaGetSymbolAddress((void**)&wvh, g_wv_h);  cudaGetSymbolAddress((void**)&wvl, g_wv_l);
    cudaGetSymbolAddress((void**)&kbh, g_kh);    cudaGetSymbolAddress((void**)&kbl, g_kl);
    cudaGetSymbolAddress((void**)&woh, g_wo_h);  cudaGetSymbolAddress((void**)&wol, g_wo_l);
    cudaGetSymbolAddress((void**)&ctxf, g_ctxf);

    const size_t out_elems  = (size_t)CM * CHID;
    const size_t attn_elems = (size_t)CB * CH * CS * CS;
    float* attn = ((size_t)out_size >= out_elems + attn_elems)
                  ? (out + out_elems) : attnfb;

    // split inputs/weights
    {
        int n4;
        n4 = (int)((size_t)CM * CHID / 4);
        split_kernel<<<(n4 + 255)/256, 256>>>(hs, hsh, hsl, n4);
        n4 = (int)((size_t)CHID * CHID / 4);
        split_kernel<<<(n4 + 255)/256, 256>>>(Wq, wqh, wql, n4);
        splitf16_kernel<<<(n4 + 255)/256, 256>>>(Wo, woh, wol, n4, 64.0f);
        n4 = (int)((size_t)CD * CHID / 4);
        split_kernel<<<(n4 + 255)/256, 256>>>(Wk, wkh, wkl, n4);
        split_kernel<<<(n4 + 255)/256, 256>>>(Wv, wvh, wvl, n4);
    }

    // QKV projections (bf16 3-pass tensor cores)
    gemm_bf16x3<<<dim3(CHID/128, CM/128), 256>>>(hsh, hsl, wqh, wql, bq, qp, CM, CHID, CHID);
    gemm_bf16x3<<<dim3(CD/128,   CM/128), 256>>>(hsh, hsl, wkh, wkl, bk, kp, CM, CD,   CHID);
    gemm_bf16x3<<<dim3(CD/128,   CM/128), 256>>>(hsh, hsl, wvh, wvl, bv, vp, CM, CD,   CHID);

    // RoPE
    {
        int total = CB * CS * (CH + 1) * CHALF;
        rope_kernel<<<(total + 255) / 256, 256>>>(pos);
    }

    // split q (reuse hs buffers), split k (bf16), transpose+split v (fp16)
    {
        int n4 = (int)((size_t)CM * CHID / 4);
        split_kernel<<<(n4 + 255)/256, 256>>>(qp, hsh, hsl, n4);
        n4 = (int)((size_t)CM * CD / 4);
        split_kernel<<<(n4 + 255)/256, 256>>>(kp, kbh, kbl, n4);
        vsplitT_kernel<<<dim3(CS/32, CD/32, CB), 256>>>();
    }

    // fused attention (bf16 QK, fp16 PV, writes fp16 ctx)
    cudaFuncSetAttribute(attn_mma_kernel,
                         cudaFuncAttributeMaxDynamicSharedMemorySize, ATTN2_SMEM);
    attn_mma_kernel<<<dim3(CS/BQ, CH, CB), 256, ATTN2_SMEM>>>(mask, attn);

    // normalize attn output
    attn_scale_kernel<<<(int)(attn_elems / 4 / 256), 256>>>(attn);

    // output projection (fp16 2-pass; Wo pre-scaled by 64)
    gemm_f16x2<<<dim3(CHID/128, CM/128), 256>>>(ctxf, woh, wol, bo, out,
                                                CM, CHID, CHID, 1.0f/64.0f);
}

// round 11
// speedup vs baseline: 1.3626x; 1.3626x over previous
#include <cuda_runtime.h>
#include <cuda_bf16.h>
#include <cstdint>
#include <math.h>

// Problem constants
#define CB   2
#define CS   2048
#define CHID 2048
#define CH   8
#define CD   256
#define CM   (CB*CS)          // 4096 rows
#define CHALF (CD/2)          // 128

// ---------------- scratch (device globals; no allocation allowed) ----------
__device__ float g_q[(size_t)CM * CHID];            // (b,s,h,d)
__device__ float g_k[(size_t)CM * CD];              // (b,s,d)   KH=1
__device__ float g_v[(size_t)CM * CD];
__device__ float g_ctx[(size_t)CM * CHID];          // (b,s,h,d)
__device__ float g_invl[(size_t)CB * CH * CS];      // 1/rowsum
__device__ float g_attn_fb[(size_t)CB * CH * CS * CS]; // fallback attn buffer

// bf16 hi/lo split buffers
__device__ __nv_bfloat16 g_hs_h[(size_t)CM * CHID];   // reused later for q split
__device__ __nv_bfloat16 g_hs_l[(size_t)CM * CHID];
__device__ __nv_bfloat16 g_wq_h[(size_t)CHID * CHID];
__device__ __nv_bfloat16 g_wq_l[(size_t)CHID * CHID];
__device__ __nv_bfloat16 g_wk_h[(size_t)CD * CHID];
__device__ __nv_bfloat16 g_wk_l[(size_t)CD * CHID];
__device__ __nv_bfloat16 g_wv_h[(size_t)CD * CHID];
__device__ __nv_bfloat16 g_wv_l[(size_t)CD * CHID];
__device__ __nv_bfloat16 g_wo_h[(size_t)CHID * CHID];
__device__ __nv_bfloat16 g_wo_l[(size_t)CHID * CHID];
__device__ __nv_bfloat16 g_ctx_h[(size_t)CM * CHID];
__device__ __nv_bfloat16 g_ctx_l[(size_t)CM * CHID];
__device__ __nv_bfloat16 g_kh[(size_t)CM * CD];
__device__ __nv_bfloat16 g_kl[(size_t)CM * CD];
__device__ __nv_bfloat16 g_vth[(size_t)CB * CD * CS];  // (b, d, s)
__device__ __nv_bfloat16 g_vtl[(size_t)CB * CD * CS];

#define g_qh g_hs_h
#define g_ql g_hs_l

// ---------------- fp32 -> bf16 hi/lo split ----------------------------------
__global__ void split_kernel(const float* __restrict__ src,
                             __nv_bfloat16* __restrict__ hi,
                             __nv_bfloat16* __restrict__ lo, int n4)
{
    int i = blockIdx.x * 256 + threadIdx.x;
    if (i >= n4) return;
    float4 v = ((const float4*)src)[i];
    __nv_bfloat16 h0 = __float2bfloat16_rn(v.x);
    __nv_bfloat16 h1 = __float2bfloat16_rn(v.y);
    __nv_bfloat16 h2 = __float2bfloat16_rn(v.z);
    __nv_bfloat16 h3 = __float2bfloat16_rn(v.w);
    __nv_bfloat16 l0 = __float2bfloat16_rn(v.x - __bfloat162float(h0));
    __nv_bfloat16 l1 = __float2bfloat16_rn(v.y - __bfloat162float(h1));
    __nv_bfloat16 l2 = __float2bfloat16_rn(v.z - __bfloat162float(h2));
    __nv_bfloat16 l3 = __float2bfloat16_rn(v.w - __bfloat162float(h3));
    __nv_bfloat162 hh0; hh0.x = h0; hh0.y = h1;
    __nv_bfloat162 hh1; hh1.x = h2; hh1.y = h3;
    __nv_bfloat162 ll0; ll0.x = l0; ll0.y = l1;
    __nv_bfloat162 ll1; ll1.x = l2; ll1.y = l3;
    ((__nv_bfloat162*)hi)[i*2]   = hh0;
    ((__nv_bfloat162*)hi)[i*2+1] = hh1;
    ((__nv_bfloat162*)lo)[i*2]   = ll0;
    ((__nv_bfloat162*)lo)[i*2+1] = ll1;
}

// ---------------- V transpose + split: (b,s,d) f32 -> (b,d,s) bf16 hi/lo ----
__global__ __launch_bounds__(256) void vsplitT_kernel()
{
    __shared__ float tile[32][33];
    int b  = blockIdx.z;
    int s0 = blockIdx.x * 32, d0 = blockIdx.y * 32;
    int tx = threadIdx.x & 31, ty = threadIdx.x >> 5;
#pragma unroll
    for (int i = 0; i < 32; i += 8)
        tile[ty + i][tx] = g_v[((size_t)(b * CS + s0 + ty + i)) * CD + d0 + tx];
    __syncthreads();
#pragma unroll
    for (int i = 0; i < 32; i += 8) {
        float v = tile[tx][ty + i];
        __nv_bfloat16 hh = __float2bfloat16_rn(v);
        size_t o = ((size_t)(b * CD + d0 + ty + i)) * CS + s0 + tx;
        g_vth[o] = hh;
        g_vtl[o] = __float2bfloat16_rn(v - __bfloat162float(hh));
    }
}

// ---------------- mma helpers -----------------------------------------------
__device__ __forceinline__ uint32_t sptr(const void* p) {
    return (uint32_t)__cvta_generic_to_shared(p);
}

#define LDM4(d0,d1,d2,d3,addr) asm volatile( \
  "ldmatrix.sync.aligned.m8n8.x4.shared.b16 {%0,%1,%2,%3}, [%4];" \
  : "=r"(d0),"=r"(d1),"=r"(d2),"=r"(d3) : "r"(addr))

#define MMA16816(c,a,b) asm volatile( \
  "mma.sync.aligned.m16n8k16.row.col.f32.bf16.bf16.f32 " \
  "{%0,%1,%2,%3}, {%4,%5,%6,%7}, {%8,%9}, {%0,%1,%2,%3};" \
  : "+f"((c)[0]),"+f"((c)[1]),"+f"((c)[2]),"+f"((c)[3]) \
  : "r"((a)[0]),"r"((a)[1]),"r"((a)[2]),"r"((a)[3]),"r"((b)[0]),"r"((b)[1]))

__device__ __forceinline__ void cpa16(uint32_t dst, const void* src) {
    asm volatile("cp.async.cg.shared.global [%0], [%1], 16;" :: "r"(dst), "l"(src));
}
#define CP_COMMIT() asm volatile("cp.async.commit_group;" ::: "memory")
#define CP_WAIT1()  asm volatile("cp.async.wait_group 1;" ::: "memory")
#define CP_WAIT0()  asm volatile("cp.async.wait_group 0;" ::: "memory")

// ---------------- tensor-core GEMM (bf16 3-pass, cp.async 2-stage) ----------
// C[m,n] = sum_k A[m,k]*W[n,k] + bias[n]. 128x128 tile, K chunk = 32.
// Dynamic smem: 2 stages x 4 arrays x [128][40] bf16 = 81,920 B.
#define GP_ARR   (128 * 40)          // elems per array
#define GP_STAGE (4 * GP_ARR)        // elems per stage
#define GP_SMEM  (2 * GP_STAGE * 2)  // bytes

__global__ __launch_bounds__(256) void gemm_bf16x3(
    const __nv_bfloat16* __restrict__ Ah, const __nv_bfloat16* __restrict__ Al,
    const __nv_bfloat16* __restrict__ Bh, const __nv_bfloat16* __restrict__ Bl,
    const float* __restrict__ bias, float* __restrict__ C,
    int M, int N, int K)
{
    extern __shared__ __align__(16) __nv_bfloat16 smg[];

    const int tid  = threadIdx.x;
    const int lane = tid & 31;
    const int warp = tid >> 5;
    const int wm = (warp & 1) * 64;
    const int wn = (warp >> 1) * 32;
    const int bm = blockIdx.y * 128;
    const int bn = blockIdx.x * 128;

    const int lr = tid >> 2;           // 0..63
    const int lc = (tid & 3) * 8;      // 0,8,16,24

    float acc[4][4][4];
#pragma unroll
    for (int i = 0; i < 4; i++)
#pragma unroll
        for (int j = 0; j < 4; j++)
#pragma unroll
            for (int r = 0; r < 4; r++) acc[i][j][r] = 0.f;

    const __nv_bfloat16* pAh = Ah + (size_t)(bm + lr) * K + lc;
    const __nv_bfloat16* pAl = Al + (size_t)(bm + lr) * K + lc;
    const __nv_bfloat16* pBh = Bh + (size_t)(bn + lr) * K + lc;
    const __nv_bfloat16* pBl = Bl + (size_t)(bn + lr) * K + lc;
    const size_t rstep = (size_t)64 * K;

    const int arow = lane & 15;
    const int acol = (lane >> 4) * 8;
    const int brow = (lane & 7) + ((lane & 16) >> 1);
    const int bcol = (lane & 8);

    const int nch = K / 32;

    // stage loader: 8 cp.asyncs of 16 B each
    auto load_stage = [&](int s, int k0) {
        uint32_t base = sptr(smg + s * GP_STAGE) + (lr * 40 + lc) * 2;
        cpa16(base,                        pAh + k0);
        cpa16(base + 64*40*2,              pAh + rstep + k0);
        cpa16(base + GP_ARR*2,             pAl + k0);
        cpa16(base + GP_ARR*2 + 64*40*2,   pAl + rstep + k0);
        cpa16(base + 2*GP_ARR*2,           pBh + k0);
        cpa16(base + 2*GP_ARR*2 + 64*40*2, pBh + rstep + k0);
        cpa16(base + 3*GP_ARR*2,           pBl + k0);
        cpa16(base + 3*GP_ARR*2 + 64*40*2, pBl + rstep + k0);
    };

    // preload chunk 0 -> stage 0
    load_stage(0, 0);
    CP_COMMIT();

    for (int i = 0; ; i++) {
        const int cur = i & 1;
        if (i + 1 < nch) {
            __syncthreads();                 // all mma(i-1) done with stage cur^1
            load_stage(cur ^ 1, (i + 1) * 32);
            CP_COMMIT();
            CP_WAIT1();                      // chunk i resident; chunk i+1 in flight
        } else {
            CP_WAIT0();
        }
        __syncthreads();                     // chunk i visible to all threads

        const __nv_bfloat16* sAh = smg + cur * GP_STAGE;
        const __nv_bfloat16* sAl = sAh + GP_ARR;
        const __nv_bfloat16* sBh = sAl + GP_ARR;
        const __nv_bfloat16* sBl = sBh + GP_ARR;

#pragma unroll
        for (int ks = 0; ks < 2; ks++) {
            const int kb = ks * 16;
            uint32_t ah[4][4], al[4][4];
#pragma unroll
            for (int mt = 0; mt < 4; mt++) {
                uint32_t adr = sptr(&sAh[(wm + mt*16 + arow) * 40 + kb + acol]);
                LDM4(ah[mt][0], ah[mt][1], ah[mt][2], ah[mt][3], adr);
                adr = sptr(&sAl[(wm + mt*16 + arow) * 40 + kb + acol]);
                LDM4(al[mt][0], al[mt][1], al[mt][2], al[mt][3], adr);
            }
            uint32_t bh[4][2], bl[4][2];
#pragma unroll
            for (int np = 0; np < 2; np++) {
                uint32_t r0, r1, r2, r3;
                uint32_t adr = sptr(&sBh[(wn + np*16 + brow) * 40 + kb + bcol]);
                LDM4(r0, r1, r2, r3, adr);
                bh[np*2][0] = r0; bh[np*2][1] = r1;
                bh[np*2+1][0] = r2; bh[np*2+1][1] = r3;
                adr = sptr(&sBl[(wn + np*16 + brow) * 40 + kb + bcol]);
                LDM4(r0, r1, r2, r3, adr);
                bl[np*2][0] = r0; bl[np*2][1] = r1;
                bl[np*2+1][0] = r2; bl[np*2+1][1] = r3;
            }
#pragma unroll
            for (int mt = 0; mt < 4; mt++)
#pragma unroll
                for (int nt = 0; nt < 4; nt++) {
                    MMA16816(acc[mt][nt], ah[mt], bh[nt]);
                    MMA16816(acc[mt][nt], ah[mt], bl[nt]);
                    MMA16816(acc[mt][nt], al[mt], bh[nt]);
                }
        }
        if (i + 1 >= nch) break;
    }

    const int crow = lane >> 2;
    const int ccol = (lane & 3) * 2;
#pragma unroll
    for (int mt = 0; mt < 4; mt++) {
#pragma unroll
        for (int nt = 0; nt < 4; nt++) {
            int gr = bm + wm + mt*16 + crow;
            int gc = bn + wn + nt*8 + ccol;
            float2 b2 = *(const float2*)(bias + gc);
            float2 o0 = make_float2(acc[mt][nt][0] + b2.x, acc[mt][nt][1] + b2.y);
            float2 o1 = make_float2(acc[mt][nt][2] + b2.x, acc[mt][nt][3] + b2.y);
            *(float2*)(C + (size_t)gr * N + gc)       = o0;
            *(float2*)(C + (size_t)(gr + 8) * N + gc) = o1;
        }
    }
}

// ---------------- RoPE -------------------------------------------------------
__global__ void rope_kernel(const int* __restrict__ pos)
{
    int idx = blockIdx.x * 256 + threadIdx.x;
    const int total = CB * CS * (CH + 1) * CHALF;
    if (idx >= total) return;
    int i  = idx & (CHALF - 1);
    int t  = idx >> 7;
    int hh = t % (CH + 1);
    int bs = t / (CH + 1);
    float p = (float)pos[bs];
    float inv = powf(10000.0f, -(float)i * (1.0f / 128.0f));
    float f = p * inv;
    float s, c;
    sincosf(f, &s, &c);
    float* ptr = (hh < CH) ? (g_q + ((size_t)bs * CH + hh) * CD)
                           : (g_k + (size_t)bs * CD);
    float x1 = ptr[i], x2 = ptr[i + CHALF];
    ptr[i]         = c * x1 - s * x2;
    ptr[i + CHALF] = s * x1 + c * x2;
}

// ---------------- tensor-core fused attention (R6-measured config) ----------
#define BQ 64
#define BK 64
#define QS 264
#define VS 72
#define ATTN2_SMEM ((2*(BQ*QS) + 2*(BK*QS) + 2*(256*VS) + 2*(BQ*VS))*2 + (128+64)*4)

__global__ __launch_bounds__(256) void attn_mma_kernel(
    const float* __restrict__ maskp, float* __restrict__ attn)
{
    extern __shared__ __align__(16) __nv_bfloat16 smb[];
    __nv_bfloat16* sQh = smb;
    __nv_bfloat16* sQl = sQh + BQ*QS;
    __nv_bfloat16* sKh = sQl + BQ*QS;
    __nv_bfloat16* sKl = sKh + BK*QS;
    __nv_bfloat16* sVh = sKl + BK*QS;
    __nv_bfloat16* sVl = sVh + 256*VS;
    __nv_bfloat16* sPh = sVl + 256*VS;
    __nv_bfloat16* sPl = sPh + BQ*VS;
    float* sRS  = (float*)(sPl + BQ*VS);
    float* sInv = sRS + 128;

    const int tid  = threadIdx.x;
    const int lane = tid & 31;
    const int warp = tid >> 5;
    const int wm = warp >> 1;
    const int wn = warp & 1;
    const int qt = blockIdx.x, h = blockIdx.y, b = blockIdx.z;
    const int r0 = qt * BQ;

    const int arow = lane & 15;
    const int acol = (lane >> 4) * 8;
    const int brow = (lane & 7) + ((lane & 16) >> 1);
    const int bcol = (lane & 8);
    const int crow = lane >> 2;
    const int ccol = (lane & 3) * 2;

#pragma unroll
    for (int it = 0; it < 8; it++) {
        int e = it * 256 + tid;
        int row = e >> 5, k8 = (e & 31) * 8;
        size_t g = ((size_t)(b * CS + r0 + row) * CH + h) * CD + k8;
        *(uint4*)&sQh[row * QS + k8] = *(const uint4*)&g_qh[g];
        *(uint4*)&sQl[row * QS + k8] = *(const uint4*)&g_ql[g];
    }

    float acc_o[16][4];
#pragma unroll
    for (int i = 0; i < 16; i++)
#pragma unroll
        for (int r = 0; r < 4; r++) acc_o[i][r] = 0.f;
    float lsum0 = 0.f, lsum1 = 0.f;
    const float scale = 0.0625f;

    for (int c0 = 0; c0 < CS; c0 += BK) {
        __syncthreads();
#pragma unroll
        for (int it = 0; it < 8; it++) {
            int e = it * 256 + tid;
            int row = e >> 5, k8 = (e & 31) * 8;
            size_t g = (size_t)(b * CS + c0 + row) * CD + k8;
            *(uint4*)&sKh[row * QS + k8] = *(const uint4*)&g_kh[g];
            *(uint4*)&sKl[row * QS + k8] = *(const uint4*)&g_kl[g];
        }
#pragma unroll
        for (int it = 0; it < 8; it++) {
            int e = it * 256 + tid;
            int d = e >> 3, kq = (e & 7) * 8;
            size_t g = (size_t)(b * CD + d) * CS + c0 + kq;
            *(uint4*)&sVh[d * VS + kq] = *(const uint4*)&g_vth[g];
            *(uint4*)&sVl[d * VS + kq] = *(const uint4*)&g_vtl[g];
        }
        __syncthreads();

        float acc_s[4][4];
#pragma unroll
        for (int j = 0; j < 4; j++)
#pragma unroll
            for (int r = 0; r < 4; r++) acc_s[j][r] = 0.f;

#pragma unroll
        for (int kk = 0; kk < CD; kk += 16) {
            uint32_t ah[4], al[4];
            uint32_t adr = sptr(&sQh[(wm*16 + arow) * QS + kk + acol]);
            LDM4(ah[0], ah[1], ah[2], ah[3], adr);
            adr = sptr(&sQl[(wm*16 + arow) * QS + kk + acol]);
            LDM4(al[0], al[1], al[2], al[3], adr);
            uint32_t bh[4][2], bl[4][2];
#pragma unroll
            for (int np = 0; np < 2; np++) {
                uint32_t r0r, r1r, r2r, r3r;
                adr = sptr(&sKh[(wn*32 + np*16 + brow) * QS + kk + bcol]);
                LDM4(r0r, r1r, r2r, r3r, adr);
                bh[np*2][0] = r0r; bh[np*2][1] = r1r;
                bh[np*2+1][0] = r2r; bh[np*2+1][1] = r3r;
                adr = sptr(&sKl[(wn*32 + np*16 + brow) * QS + kk + bcol]);
                LDM4(r0r, r1r, r2r, r3r, adr);
                bl[np*2][0] = r0r; bl[np*2][1] = r1r;
                bl[np*2+1][0] = r2r; bl[np*2+1][1] = r3r;
            }
#pragma unroll
            for (int nt = 0; nt < 4; nt++) {
                MMA16816(acc_s[nt], ah, bh[nt]);
                MMA16816(acc_s[nt], ah, bl[nt]);
                MMA16816(acc_s[nt], al, bh[nt]);
            }
        }

        {
            int r = wm*16 + crow;
            size_t rb0 = ((size_t)(b * CH + h) * CS + r0 + r) * CS;
            size_t rb1 = rb0 + (size_t)8 * CS;
#pragma unroll
            for (int nt = 0; nt < 4; nt++) {
                int kl = wn*32 + nt*8 + ccol;
                int kg = c0 + kl;
                float m0 = maskp[b * CS + kg];
                float m1 = maskp[b * CS + kg + 1];
                float p00 = __expf(acc_s[nt][0] * scale + m0);
                float p01 = __expf(acc_s[nt][1] * scale + m1);
                float p10 = __expf(acc_s[nt][2] * scale + m0);
                float p11 = __expf(acc_s[nt][3] * scale + m1);
                lsum0 += p00 + p01;
                lsum1 += p10 + p11;
                *(float2*)&attn[rb0 + kg] = make_float2(p00, p01);
                *(float2*)&attn[rb1 + kg] = make_float2(p10, p11);
                __nv_bfloat16 h00 = __float2bfloat16_rn(p00);
                __nv_bfloat16 h01 = __float2bfloat16_rn(p01);
                __nv_bfloat16 h10 = __float2bfloat16_rn(p10);
                __nv_bfloat16 h11 = __float2bfloat16_rn(p11);
                __nv_bfloat162 hp0; hp0.x = h00; hp0.y = h01;
                __nv_bfloat162 hp1; hp1.x = h10; hp1.y = h11;
                __nv_bfloat162 lp0;
                lp0.x = __float2bfloat16_rn(p00 - __bfloat162float(h00));
                lp0.y = __float2bfloat16_rn(p01 - __bfloat162float(h01));
                __nv_bfloat162 lp1;
                lp1.x = __float2bfloat16_rn(p10 - __bfloat162float(h10));
                lp1.y = __float2bfloat16_rn(p11 - __bfloat162float(h11));
                *(__nv_bfloat162*)&sPh[r * VS + kl]       = hp0;
                *(__nv_bfloat162*)&sPh[(r + 8) * VS + kl] = hp1;
                *(__nv_bfloat162*)&sPl[r * VS + kl]       = lp0;
                *(__nv_bfloat162*)&sPl[(r + 8) * VS + kl] = lp1;
            }
        }
        __syncthreads();

#pragma unroll
        for (int kc = 0; kc < 4; kc++) {
            uint32_t ph[4], pl[4];
            uint32_t adr = sptr(&sPh[(wm*16 + arow) * VS + kc*16 + acol]);
            LDM4(ph[0], ph[1], ph[2], ph[3], adr);
            adr = sptr(&sPl[(wm*16 + arow) * VS + kc*16 + acol]);
            LDM4(pl[0], pl[1], pl[2], pl[3], adr);
#pragma unroll
            for (int np = 0; np < 8; np++) {
                uint32_t r0r, r1r, r2r, r3r;
                uint32_t vh0[2], vh1[2], vl0[2], vl1[2];
                adr = sptr(&sVh[(wn*128 + np*16 + brow) * VS + kc*16 + bcol]);
                LDM4(r0r, r1r, r2r, r3r, adr);
                vh0[0] = r0r; vh0[1] = r1r; vh1[0] = r2r; vh1[1] = r3r;
                adr = sptr(&sVl[(wn*128 + np*16 + brow) * VS + kc*16 + bcol]);
                LDM4(r0r, r1r, r2r, r3r, adr);
                vl0[0] = r0r; vl0[1] = r1r; vl1[0] = r2r; vl1[1] = r3r;
                MMA16816(acc_o[np*2],   ph, vh0);
                MMA16816(acc_o[np*2],   ph, vl0);
                MMA16816(acc_o[np*2],   pl, vh0);
                MMA16816(acc_o[np*2+1], ph, vh1);
                MMA16816(acc_o[np*2+1], ph, vl1);
                MMA16816(acc_o[np*2+1], pl, vh1);
            }
        }
    }

    lsum0 += __shfl_xor_sync(0xffffffff, lsum0, 1);
    lsum0 += __shfl_xor_sync(0xffffffff, lsum0, 2);
    lsum1 += __shfl_xor_sync(0xffffffff, lsum1, 1);
    lsum1 += __shfl_xor_sync(0xffffffff, lsum1, 2);
    if ((lane & 3) == 0) {
        sRS[(wm*16 + crow) * 2 + wn]     = lsum0;
        sRS[(wm*16 + crow + 8) * 2 + wn] = lsum1;
    }
    __syncthreads();
    if (tid < 64) {
        float inv = 1.0f / (sRS[tid*2] + sRS[tid*2 + 1]);
        sInv[tid] = inv;
        g_invl[((size_t)(b * CH + h)) * CS + r0 + tid] = inv;
    }
    __syncthreads();

    {
        int r = wm*16 + crow;
        float inv0 = sInv[r], inv1 = sInv[r + 8];
        size_t ob0 = ((size_t)(b * CS + r0 + r) * CH + h) * CD;
        size_t ob1 = ((size_t)(b * CS + r0 + r + 8) * CH + h) * CD;
#pragma unroll
        for (int nt = 0; nt < 16; nt++) {
            int d = wn*128 + nt*8 + ccol;
            *(float2*)&g_ctx[ob0 + d] = make_float2(acc_o[nt][0]*inv0, acc_o[nt][1]*inv0);
            *(float2*)&g_ctx[ob1 + d] = make_float2(acc_o[nt][2]*inv1, acc_o[nt][3]*inv1);
        }
    }
}

// ---------------- normalize attn rows by 1/l --------------------------------
__global__ void attn_scale_kernel(float* __restrict__ attn)
{
    size_t i = (size_t)blockIdx.x * 256 + threadIdx.x;
    float4* a4 = (float4*)attn;
    size_t row = i >> 9;
    float inv = g_invl[row];
    float4 v = a4[i];
    v.x *= inv; v.y *= inv; v.z *= inv; v.w *= inv;
    a4[i] = v;
}

// ---------------- launch ----------------------------------------------------
extern "C" void kernel_launch(void* const* d_in, const int* in_sizes, int n_in,
                              void* d_out, int out_size)
{
    const float* hs   = (const float*)d_in[0];
    const float* mask = (const float*)d_in[1];
    const int*   pos  = (const int*)  d_in[2];
    const float* Wq   = (const float*)d_in[3];
    const float* bq   = (const float*)d_in[4];
    const float* Wk   = (const float*)d_in[5];
    const float* bk   = (const float*)d_in[6];
    const float* Wv   = (const float*)d_in[7];
    const float* bv   = (const float*)d_in[8];
    const float* Wo   = (const float*)d_in[9];
    const float* bo   = (const float*)d_in[10];
    float* out = (float*)d_out;

    float *qp, *kp, *vp, *ctxp, *attnfb;
    cudaGetSymbolAddress((void**)&qp,     g_q);
    cudaGetSymbolAddress((void**)&kp,     g_k);
    cudaGetSymbolAddress((void**)&vp,     g_v);
    cudaGetSymbolAddress((void**)&ctxp,   g_ctx);
    cudaGetSymbolAddress((void**)&attnfb, g_attn_fb);

    __nv_bfloat16 *hsh, *hsl, *wqh, *wql, *wkh, *wkl, *wvh, *wvl, *woh, *wol;
    __nv_bfloat16 *cxh, *cxl, *kbh, *kbl;
    cudaGetSymbolAddress((void**)&hsh, g_hs_h);  cudaGetSymbolAddress((void**)&hsl, g_hs_l);
    cudaGetSymbolAddress((void**)&wqh, g_wq_h);  cudaGetSymbolAddress((void**)&wql, g_wq_l);
    cudaGetSymbolAddress((void**)&wkh, g_wk_h);  cudaGetSymbolAddress((void**)&wkl, g_wk_l);
    cudaGetSymbolAddress((void**)&wvh, g_wv_h);  cudaGetSymbolAddress((void**)&wvl, g_wv_l);
    cudaGetSymbolAddress((void**)&woh, g_wo_h);  cudaGetSymbolAddress((void**)&wol, g_wo_l);
    cudaGetSymbolAddress((void**)&cxh, g_ctx_h); cudaGetSymbolAddress((void**)&cxl, g_ctx_l);
    cudaGetSymbolAddress((void**)&kbh, g_kh);    cudaGetSymbolAddress((void**)&kbl, g_kl);

    const size_t out_elems  = (size_t)CM * CHID;
    const size_t attn_elems = (size_t)CB * CH * CS * CS;
    float* attn = ((size_t)out_size >= out_elems + attn_elems)
                  ? (out + out_elems) : attnfb;

    // split inputs/weights into bf16 hi/lo
    {
        int n4;
        n4 = (int)((size_t)CM * CHID / 4);
        split_kernel<<<(n4 + 255)/256, 256>>>(hs, hsh, hsl, n4);
        n4 = (int)((size_t)CHID * CHID / 4);
        split_kernel<<<(n4 + 255)/256, 256>>>(Wq, wqh, wql, n4);
        split_kernel<<<(n4 + 255)/256, 256>>>(Wo, woh, wol, n4);
        n4 = (int)((size_t)CD * CHID / 4);
        split_kernel<<<(n4 + 255)/256, 256>>>(Wk, wkh, wkl, n4);
        split_kernel<<<(n4 + 255)/256, 256>>>(Wv, wvh, wvl, n4);
    }

    // QKV projections (cp.async-pipelined tensor-core GEMM)
    cudaFuncSetAttribute(gemm_bf16x3, cudaFuncAttributeMaxDynamicSharedMemorySize, GP_SMEM);
    gemm_bf16x3<<<dim3(CHID/128, CM/128), 256, GP_SMEM>>>(hsh, hsl, wqh, wql, bq, qp, CM, CHID, CHID);
    gemm_bf16x3<<<dim3(CD/128,   CM/128), 256, GP_SMEM>>>(hsh, hsl, wkh, wkl, bk, kp, CM, CD,   CHID);
    gemm_bf16x3<<<dim3(CD/128,   CM/128), 256, GP_SMEM>>>(hsh, hsl, wvh, wvl, bv, vp, CM, CD,   CHID);

    // RoPE
    {
        int total = CB * CS * (CH + 1) * CHALF;
        rope_kernel<<<(total + 255) / 256, 256>>>(pos);
    }

    // split q (reuse hs buffers), split k, transpose+split v
    {
        int n4 = (int)((size_t)CM * CHID / 4);
        split_kernel<<<(n4 + 255)/256, 256>>>(qp, hsh, hsl, n4);
        n4 = (int)((size_t)CM * CD / 4);
        split_kernel<<<(n4 + 255)/256, 256>>>(kp, kbh, kbl, n4);
        vsplitT_kernel<<<dim3(CS/32, CD/32, CB), 256>>>();
    }

    // fused attention (bf16 3-pass QK and PV — R6-measured config)
    cudaFuncSetAttribute(attn_mma_kernel,
                         cudaFuncAttributeMaxDynamicSharedMemorySize, ATTN2_SMEM);
    attn_mma_kernel<<<dim3(CS/BQ, CH, CB), 256, ATTN2_SMEM>>>(mask, attn);

    // normalize attn output
    attn_scale_kernel<<<(int)(attn_elems / 4 / 256), 256>>>(attn);

    // split context, output projection
    {
        int n4 = (int)((size_t)CM * CHID / 4);
        split_kernel<<<(n4 + 255)/256, 256>>>(ctxp, cxh, cxl, n4);
    }
    gemm_bf16x3<<<dim3(CHID/128, CM/128), 256, GP_SMEM>>>(cxh, cxl, woh, wol, bo, out, CM, CHID, CHID);
}

// round 15
// speedup vs baseline: 1.4433x; 1.0593x over previous
#include <cuda_runtime.h>
#include <cuda_bf16.h>
#include <cstdint>
#include <math.h>

// Problem constants
#define CB   2
#define CS   2048
#define CHID 2048
#define CH   8
#define CD   256
#define CM   (CB*CS)          // 4096 rows
#define CHALF (CD/2)          // 128
#define NQKV (CHID + 2*CD)    // 2560 fused projection width

// ---------------- scratch (device globals; no allocation allowed) ----------
__device__ float g_qkv[(size_t)CM * NQKV];          // [q(2048) | k(256) | v(256)]
__device__ float g_ctx[(size_t)CM * CHID];          // (b,s,h,d)
__device__ float g_invl[(size_t)CB * CH * CS];      // 1/rowsum
__device__ float g_bqkv[NQKV];                      // fused bias
__device__ float g_attn_fb[(size_t)CB * CH * CS * CS]; // fallback attn buffer

// bf16 hi/lo split buffers
__device__ __nv_bfloat16 g_hs_h[(size_t)CM * CHID];   // reused later for q split
__device__ __nv_bfloat16 g_hs_l[(size_t)CM * CHID];
__device__ __nv_bfloat16 g_wqkv_h[(size_t)NQKV * CHID];
__device__ __nv_bfloat16 g_wqkv_l[(size_t)NQKV * CHID];
__device__ __nv_bfloat16 g_wo_h[(size_t)CHID * CHID];
__device__ __nv_bfloat16 g_wo_l[(size_t)CHID * CHID];
__device__ __nv_bfloat16 g_ctx_h[(size_t)CM * CHID];
__device__ __nv_bfloat16 g_ctx_l[(size_t)CM * CHID];
__device__ __nv_bfloat16 g_kh[(size_t)CM * CD];
__device__ __nv_bfloat16 g_kl[(size_t)CM * CD];
__device__ __nv_bfloat16 g_vth[(size_t)CB * CD * CS];  // (b, d, s)
__device__ __nv_bfloat16 g_vtl[(size_t)CB * CD * CS];

#define g_qh g_hs_h
#define g_ql g_hs_l

// ---------------- fp32 -> bf16 hi/lo split (packed) --------------------------
__global__ void split_kernel(const float* __restrict__ src,
                             __nv_bfloat16* __restrict__ hi,
                             __nv_bfloat16* __restrict__ lo, int n4)
{
    int i = blockIdx.x * 256 + threadIdx.x;
    if (i >= n4) return;
    float4 v = ((const float4*)src)[i];
    __nv_bfloat16 h0 = __float2bfloat16_rn(v.x);
    __nv_bfloat16 h1 = __float2bfloat16_rn(v.y);
    __nv_bfloat16 h2 = __float2bfloat16_rn(v.z);
    __nv_bfloat16 h3 = __float2bfloat16_rn(v.w);
    __nv_bfloat16 l0 = __float2bfloat16_rn(v.x - __bfloat162float(h0));
    __nv_bfloat16 l1 = __float2bfloat16_rn(v.y - __bfloat162float(h1));
    __nv_bfloat16 l2 = __float2bfloat16_rn(v.z - __bfloat162float(h2));
    __nv_bfloat16 l3 = __float2bfloat16_rn(v.w - __bfloat162float(h3));
    __nv_bfloat162 hh0; hh0.x = h0; hh0.y = h1;
    __nv_bfloat162 hh1; hh1.x = h2; hh1.y = h3;
    __nv_bfloat162 ll0; ll0.x = l0; ll0.y = l1;
    __nv_bfloat162 ll1; ll1.x = l2; ll1.y = l3;
    ((__nv_bfloat162*)hi)[i*2]   = hh0;
    ((__nv_bfloat162*)hi)[i*2+1] = hh1;
    ((__nv_bfloat162*)lo)[i*2]   = ll0;
    ((__nv_bfloat162*)lo)[i*2+1] = ll1;
}

// ---------------- strided fp32 -> bf16 hi/lo split ---------------------------
__global__ void split_strided_kernel(const float* __restrict__ src,
                                     __nv_bfloat16* __restrict__ hi,
                                     __nv_bfloat16* __restrict__ lo,
                                     int rows, int src_ld, int c0, int cols)
{
    int i = blockIdx.x * 256 + threadIdx.x;
    int c4n = cols >> 2;
    if (i >= rows * c4n) return;
    int row = i / c4n, c4 = i % c4n;
    float4 v = *(const float4*)(src + (size_t)row * src_ld + c0 + c4 * 4);
    __nv_bfloat16 h0 = __float2bfloat16_rn(v.x);
    __nv_bfloat16 h1 = __float2bfloat16_rn(v.y);
    __nv_bfloat16 h2 = __float2bfloat16_rn(v.z);
    __nv_bfloat16 h3 = __float2bfloat16_rn(v.w);
    __nv_bfloat162 hh0; hh0.x = h0; hh0.y = h1;
    __nv_bfloat162 hh1; hh1.x = h2; hh1.y = h3;
    __nv_bfloat162 ll0;
    ll0.x = __float2bfloat16_rn(v.x - __bfloat162float(h0));
    ll0.y = __float2bfloat16_rn(v.y - __bfloat162float(h1));
    __nv_bfloat162 ll1;
    ll1.x = __float2bfloat16_rn(v.z - __bfloat162float(h2));
    ll1.y = __float2bfloat16_rn(v.w - __bfloat162float(h3));
    size_t o = (size_t)row * cols + c4 * 4;
    *(__nv_bfloat162*)(hi + o)     = hh0;
    *(__nv_bfloat162*)(hi + o + 2) = hh1;
    *(__nv_bfloat162*)(lo + o)     = ll0;
    *(__nv_bfloat162*)(lo + o + 2) = ll1;
}

// ---------------- V transpose + split: strided qkv -> (b,d,s) bf16 hi/lo ----
__global__ __launch_bounds__(256) void vsplitT_kernel()
{
    __shared__ float tile[32][33];
    int b  = blockIdx.z;
    int s0 = blockIdx.x * 32, d0 = blockIdx.y * 32;
    int tx = threadIdx.x & 31, ty = threadIdx.x >> 5;
#pragma unroll
    for (int i = 0; i < 32; i += 8)
        tile[ty + i][tx] =
            g_qkv[((size_t)(b * CS + s0 + ty + i)) * NQKV + CHID + CD + d0 + tx];
    __syncthreads();
#pragma unroll
    for (int i = 0; i < 32; i += 8) {
        float v = tile[tx][ty + i];
        __nv_bfloat16 hh = __float2bfloat16_rn(v);
        size_t o = ((size_t)(b * CD + d0 + ty + i)) * CS + s0 + tx;
        g_vth[o] = hh;
        g_vtl[o] = __float2bfloat16_rn(v - __bfloat162float(hh));
    }
}

// ---------------- mma helpers -----------------------------------------------
__device__ __forceinline__ uint32_t sptr(const void* p) {
    return (uint32_t)__cvta_generic_to_shared(p);
}

#define LDM4(d0,d1,d2,d3,addr) asm volatile( \
  "ldmatrix.sync.aligned.m8n8.x4.shared.b16 {%0,%1,%2,%3}, [%4];" \
  : "=r"(d0),"=r"(d1),"=r"(d2),"=r"(d3) : "r"(addr))

#define MMA16816(c,a,b) asm volatile( \
  "mma.sync.aligned.m16n8k16.row.col.f32.bf16.bf16.f32 " \
  "{%0,%1,%2,%3}, {%4,%5,%6,%7}, {%8,%9}, {%0,%1,%2,%3};" \
  : "+f"((c)[0]),"+f"((c)[1]),"+f"((c)[2]),"+f"((c)[3]) \
  : "r"((a)[0]),"r"((a)[1]),"r"((a)[2]),"r"((a)[3]),"r"((b)[0]),"r"((b)[1]))

__device__ __forceinline__ void cpa16(uint32_t dst, const void* src) {
    asm volatile("cp.async.cg.shared.global [%0], [%1], 16;" :: "r"(dst), "l"(src));
}
#define CP_COMMIT() asm volatile("cp.async.commit_group;" ::: "memory")
#define CP_WAIT1()  asm volatile("cp.async.wait_group 1;" ::: "memory")
#define CP_WAIT0()  asm volatile("cp.async.wait_group 0;" ::: "memory")

// ---------------- tensor-core GEMM (bf16 3-pass, cp.async 2-stage) ----------
#define GP_ARR   (128 * 40)
#define GP_STAGE (4 * GP_ARR)
#define GP_SMEM  (2 * GP_STAGE * 2)

__global__ __launch_bounds__(256) void gemm_bf16x3(
    const __nv_bfloat16* __restrict__ Ah, const __nv_bfloat16* __restrict__ Al,
    const __nv_bfloat16* __restrict__ Bh, const __nv_bfloat16* __restrict__ Bl,
    const float* __restrict__ bias, float* __restrict__ C,
    int M, int N, int K)
{
    extern __shared__ __align__(16) __nv_bfloat16 smg[];

    const int tid  = threadIdx.x;
    const int lane = tid & 31;
    const int warp = tid >> 5;
    const int wm = (warp & 1) * 64;
    const int wn = (warp >> 1) * 32;
    const int bm = blockIdx.y * 128;
    const int bn = blockIdx.x * 128;

    const int lr = tid >> 2;
    const int lc = (tid & 3) * 8;

    float acc[4][4][4];
#pragma unroll
    for (int i = 0; i < 4; i++)
#pragma unroll
        for (int j = 0; j < 4; j++)
#pragma unroll
            for (int r = 0; r < 4; r++) acc[i][j][r] = 0.f;

    const __nv_bfloat16* pAh = Ah + (size_t)(bm + lr) * K + lc;
    const __nv_bfloat16* pAl = Al + (size_t)(bm + lr) * K + lc;
    const __nv_bfloat16* pBh = Bh + (size_t)(bn + lr) * K + lc;
    const __nv_bfloat16* pBl = Bl + (size_t)(bn + lr) * K + lc;
    const size_t rstep = (size_t)64 * K;

    const int arow = lane & 15;
    const int acol = (lane >> 4) * 8;
    const int brow = (lane & 7) + ((lane & 16) >> 1);
    const int bcol = (lane & 8);

    const int nch = K / 32;

    auto load_stage = [&](int s, int k0) {
        uint32_t base = sptr(smg + s * GP_STAGE) + (lr * 40 + lc) * 2;
        cpa16(base,                        pAh + k0);
        cpa16(base + 64*40*2,              pAh + rstep + k0);
        cpa16(base + GP_ARR*2,             pAl + k0);
        cpa16(base + GP_ARR*2 + 64*40*2,   pAl + rstep + k0);
        cpa16(base + 2*GP_ARR*2,           pBh + k0);
        cpa16(base + 2*GP_ARR*2 + 64*40*2, pBh + rstep + k0);
        cpa16(base + 3*GP_ARR*2,           pBl + k0);
        cpa16(base + 3*GP_ARR*2 + 64*40*2, pBl + rstep + k0);
    };

    load_stage(0, 0);
    CP_COMMIT();

    for (int i = 0; ; i++) {
        const int cur = i & 1;
        if (i + 1 < nch) {
            __syncthreads();
            load_stage(cur ^ 1, (i + 1) * 32);
            CP_COMMIT();
            CP_WAIT1();
        } else {
            CP_WAIT0();
        }
        __syncthreads();

        const __nv_bfloat16* sAh = smg + cur * GP_STAGE;
        const __nv_bfloat16* sAl = sAh + GP_ARR;
        const __nv_bfloat16* sBh = sAl + GP_ARR;
        const __nv_bfloat16* sBl = sBh + GP_ARR;

#pragma unroll
        for (int ks = 0; ks < 2; ks++) {
            const int kb = ks * 16;
            uint32_t ah[4][4], al[4][4];
#pragma unroll
            for (int mt = 0; mt < 4; mt++) {
                uint32_t adr = sptr(&sAh[(wm + mt*16 + arow) * 40 + kb + acol]);
                LDM4(ah[mt][0], ah[mt][1], ah[mt][2], ah[mt][3], adr);
                adr = sptr(&sAl[(wm + mt*16 + arow) * 40 + kb + acol]);
                LDM4(al[mt][0], al[mt][1], al[mt][2], al[mt][3], adr);
            }
            uint32_t bh[4][2], bl[4][2];
#pragma unroll
            for (int np = 0; np < 2; np++) {
                uint32_t r0, r1, r2, r3;
                uint32_t adr = sptr(&sBh[(wn + np*16 + brow) * 40 + kb + bcol]);
                LDM4(r0, r1, r2, r3, adr);
                bh[np*2][0] = r0; bh[np*2][1] = r1;
                bh[np*2+1][0] = r2; bh[np*2+1][1] = r3;
                adr = sptr(&sBl[(wn + np*16 + brow) * 40 + kb + bcol]);
                LDM4(r0, r1, r2, r3, adr);
                bl[np*2][0] = r0; bl[np*2][1] = r1;
                bl[np*2+1][0] = r2; bl[np*2+1][1] = r3;
            }
#pragma unroll
            for (int mt = 0; mt < 4; mt++)
#pragma unroll
                for (int nt = 0; nt < 4; nt++) {
                    MMA16816(acc[mt][nt], ah[mt], bh[nt]);
                    MMA16816(acc[mt][nt], ah[mt], bl[nt]);
                    MMA16816(acc[mt][nt], al[mt], bh[nt]);
                }
        }
        if (i + 1 >= nch) break;
    }

    const int crow = lane >> 2;
    const int ccol = (lane & 3) * 2;
#pragma unroll
    for (int mt = 0; mt < 4; mt++) {
#pragma unroll
        for (int nt = 0; nt < 4; nt++) {
            int gr = bm + wm + mt*16 + crow;
            int gc = bn + wn + nt*8 + ccol;
            float2 b2 = *(const float2*)(bias + gc);
            float2 o0 = make_float2(acc[mt][nt][0] + b2.x, acc[mt][nt][1] + b2.y);
            float2 o1 = make_float2(acc[mt][nt][2] + b2.x, acc[mt][nt][3] + b2.y);
            *(float2*)(C + (size_t)gr * N + gc)       = o0;
            *(float2*)(C + (size_t)(gr + 8) * N + gc) = o1;
        }
    }
}

// ---------------- RoPE (on fused qkv buffer) ---------------------------------
__global__ void rope_kernel(const int* __restrict__ pos)
{
    int idx = blockIdx.x * 256 + threadIdx.x;
    const int total = CB * CS * (CH + 1) * CHALF;
    if (idx >= total) return;
    int i  = idx & (CHALF - 1);
    int t  = idx >> 7;
    int hh = t % (CH + 1);
    int bs = t / (CH + 1);
    float p = (float)pos[bs];
    float inv = powf(10000.0f, -(float)i * (1.0f / 128.0f));
    float f = p * inv;
    float s, c;
    sincosf(f, &s, &c);
    float* ptr = g_qkv + (size_t)bs * NQKV + ((hh < CH) ? hh * CD : CHID);
    float x1 = ptr[i], x2 = ptr[i + CHALF];
    ptr[i]         = c * x1 - s * x2;
    ptr[i + CHALF] = s * x1 + c * x2;
}

// ---------------- tensor-core fused attention --------------------------------
// QK^T: bf16 3-pass. PV: bf16 3-pass (P hi/lo, V hi/lo) — measured-correct.
#define BQ 64
#define BK 64
#define QS 264
#define VS 72
#define ATTN2_SMEM ((2*(BQ*QS) + 2*(BK*QS) + 2*(256*VS) + 2*(BQ*VS))*2 + (128+64)*4)

__global__ __launch_bounds__(256) void attn_mma_kernel(
    const float* __restrict__ maskp, float* __restrict__ attn)
{
    extern __shared__ __align__(16) __nv_bfloat16 smb[];
    __nv_bfloat16* sQh = smb;
    __nv_bfloat16* sQl = sQh + BQ*QS;
    __nv_bfloat16* sKh = sQl + BQ*QS;
    __nv_bfloat16* sKl = sKh + BK*QS;
    __nv_bfloat16* sVh = sKl + BK*QS;
    __nv_bfloat16* sVl = sVh + 256*VS;
    __nv_bfloat16* sPh = sVl + 256*VS;
    __nv_bfloat16* sPl = sPh + BQ*VS;
    float* sRS  = (float*)(sPl + BQ*VS);
    float* sInv = sRS + 128;

    const int tid  = threadIdx.x;
    const int lane = tid & 31;
    const int warp = tid >> 5;
    const int wm = warp >> 1;
    const int wn = warp & 1;
    const int qt = blockIdx.x, h = blockIdx.y, b = blockIdx.z;
    const int r0 = qt * BQ;

    const int arow = lane & 15;
    const int acol = (lane >> 4) * 8;
    const int brow = (lane & 7) + ((lane & 16) >> 1);
    const int bcol = (lane & 8);
    const int crow = lane >> 2;
    const int ccol = (lane & 3) * 2;

#pragma unroll
    for (int it = 0; it < 8; it++) {
        int e = it * 256 + tid;
        int row = e >> 5, k8 = (e & 31) * 8;
        size_t g = ((size_t)(b * CS + r0 + row) * CH + h) * CD + k8;
        *(uint4*)&sQh[row * QS + k8] = *(const uint4*)&g_qh[g];
        *(uint4*)&sQl[row * QS + k8] = *(const uint4*)&g_ql[g];
    }

    float acc_o[16][4];
#pragma unroll
    for (int i = 0; i < 16; i++)
#pragma unroll
        for (int r = 0; r < 4; r++) acc_o[i][r] = 0.f;
    float lsum0 = 0.f, lsum1 = 0.f;
    const float scale = 0.0625f;

    for (int c0 = 0; c0 < CS; c0 += BK) {
        __syncthreads();
#pragma unroll
        for (int it = 0; it < 8; it++) {
            int e = it * 256 + tid;
            int row = e >> 5, k8 = (e & 31) * 8;
            size_t g = (size_t)(b * CS + c0 + row) * CD + k8;
            *(uint4*)&sKh[row * QS + k8] = *(const uint4*)&g_kh[g];
            *(uint4*)&sKl[row * QS + k8] = *(const uint4*)&g_kl[g];
        }
#pragma unroll
        for (int it = 0; it < 8; it++) {
            int e = it * 256 + tid;
            int d = e >> 3, kq = (e & 7) * 8;
            size_t g = (size_t)(b * CD + d) * CS + c0 + kq;
            *(uint4*)&sVh[d * VS + kq] = *(const uint4*)&g_vth[g];
            *(uint4*)&sVl[d * VS + kq] = *(const uint4*)&g_vtl[g];
        }
        __syncthreads();

        // ---- QK^T (bf16 3-pass) ----
        float acc_s[4][4];
#pragma unroll
        for (int j = 0; j < 4; j++)
#pragma unroll
            for (int r = 0; r < 4; r++) acc_s[j][r] = 0.f;

#pragma unroll
        for (int kk = 0; kk < CD; kk += 16) {
            uint32_t ah[4], al[4];
            uint32_t adr = sptr(&sQh[(wm*16 + arow) * QS + kk + acol]);
            LDM4(ah[0], ah[1], ah[2], ah[3], adr);
            adr = sptr(&sQl[(wm*16 + arow) * QS + kk + acol]);
            LDM4(al[0], al[1], al[2], al[3], adr);
            uint32_t bh[4][2], bl[4][2];
#pragma unroll
            for (int np = 0; np < 2; np++) {
                uint32_t r0r, r1r, r2r, r3r;
                adr = sptr(&sKh[(wn*32 + np*16 + brow) * QS + kk + bcol]);
                LDM4(r0r, r1r, r2r, r3r, adr);
                bh[np*2][0] = r0r; bh[np*2][1] = r1r;
                bh[np*2+1][0] = r2r; bh[np*2+1][1] = r3r;
                adr = sptr(&sKl[(wn*32 + np*16 + brow) * QS + kk + bcol]);
                LDM4(r0r, r1r, r2r, r3r, adr);
                bl[np*2][0] = r0r; bl[np*2][1] = r1r;
                bl[np*2+1][0] = r2r; bl[np*2+1][1] = r3r;
            }
#pragma unroll
            for (int nt = 0; nt < 4; nt++) {
                MMA16816(acc_s[nt], ah, bh[nt]);
                MMA16816(acc_s[nt], ah, bl[nt]);
                MMA16816(acc_s[nt], al, bh[nt]);
            }
        }

        // ---- exp + attn write + stage P (hi/lo) ----
        {
            int r = wm*16 + crow;
            size_t rb0 = ((size_t)(b * CH + h) * CS + r0 + r) * CS;
            size_t rb1 = rb0 + (size_t)8 * CS;
#pragma unroll
            for (int nt = 0; nt < 4; nt++) {
                int kl = wn*32 + nt*8 + ccol;
                int kg = c0 + kl;
                float m0 = maskp[b * CS + kg];
                float m1 = maskp[b * CS + kg + 1];
                float p00 = __expf(acc_s[nt][0] * scale + m0);
                float p01 = __expf(acc_s[nt][1] * scale + m1);
                float p10 = __expf(acc_s[nt][2] * scale + m0);
                float p11 = __expf(acc_s[nt][3] * scale + m1);
                lsum0 += p00 + p01;
                lsum1 += p10 + p11;
                *(float2*)&attn[rb0 + kg] = make_float2(p00, p01);
                *(float2*)&attn[rb1 + kg] = make_float2(p10, p11);
                __nv_bfloat16 h00 = __float2bfloat16_rn(p00);
                __nv_bfloat16 h01 = __float2bfloat16_rn(p01);
                __nv_bfloat16 h10 = __float2bfloat16_rn(p10);
                __nv_bfloat16 h11 = __float2bfloat16_rn(p11);
                __nv_bfloat162 hp0; hp0.x = h00; hp0.y = h01;
                __nv_bfloat162 hp1; hp1.x = h10; hp1.y = h11;
                __nv_bfloat162 lp0;
                lp0.x = __float2bfloat16_rn(p00 - __bfloat162float(h00));
                lp0.y = __float2bfloat16_rn(p01 - __bfloat162float(h01));
                __nv_bfloat162 lp1;
                lp1.x = __float2bfloat16_rn(p10 - __bfloat162float(h10));
                lp1.y = __float2bfloat16_rn(p11 - __bfloat162float(h11));
                *(__nv_bfloat162*)&sPh[r * VS + kl]       = hp0;
                *(__nv_bfloat162*)&sPh[(r + 8) * VS + kl] = hp1;
                *(__nv_bfloat162*)&sPl[r * VS + kl]       = lp0;
                *(__nv_bfloat162*)&sPl[(r + 8) * VS + kl] = lp1;
            }
        }
        __syncthreads();

        // ---- PV (bf16 3-pass: Ph·Vh + Ph·Vl + Pl·Vh) ----
#pragma unroll
        for (int kc = 0; kc < 4; kc++) {
            uint32_t ph[4], pl[4];
            uint32_t adr = sptr(&sPh[(wm*16 + arow) * VS + kc*16 + acol]);
            LDM4(ph[0], ph[1], ph[2], ph[3], adr);
            adr = sptr(&sPl[(wm*16 + arow) * VS + kc*16 + acol]);
            LDM4(pl[0], pl[1], pl[2], pl[3], adr);
#pragma unroll
            for (int np = 0; np < 8; np++) {
                uint32_t r0r, r1r, r2r, r3r;
                uint32_t vh0[2], vh1[2], vl0[2], vl1[2];
                adr = sptr(&sVh[(wn*128 + np*16 + brow) * VS + kc*16 + bcol]);
                LDM4(r0r, r1r, r2r, r3r, adr);
                vh0[0] = r0r; vh0[1] = r1r; vh1[0] = r2r; vh1[1] = r3r;
                adr = sptr(&sVl[(wn*128 + np*16 + brow) * VS + kc*16 + bcol]);
                LDM4(r0r, r1r, r2r, r3r, adr);
                vl0[0] = r0r; vl0[1] = r1r; vl1[0] = r2r; vl1[1] = r3r;
                MMA16816(acc_o[np*2],   ph, vh0);
                MMA16816(acc_o[np*2],   ph, vl0);
                MMA16816(acc_o[np*2],   pl, vh0);
                MMA16816(acc_o[np*2+1], ph, vh1);
                MMA16816(acc_o[np*2+1], ph, vl1);
                MMA16816(acc_o[np*2+1], pl, vh1);
            }
        }
    }

    lsum0 += __shfl_xor_sync(0xffffffff, lsum0, 1);
    lsum0 += __shfl_xor_sync(0xffffffff, lsum0, 2);
    lsum1 += __shfl_xor_sync(0xffffffff, lsum1, 1);
    lsum1 += __shfl_xor_sync(0xffffffff, lsum1, 2);
    if ((lane & 3) == 0) {
        sRS[(wm*16 + crow) * 2 + wn]     = lsum0;
        sRS[(wm*16 + crow + 8) * 2 + wn] = lsum1;
    }
    __syncthreads();
    if (tid < 64) {
        float inv = 1.0f / (sRS[tid*2] + sRS[tid*2 + 1]);
        sInv[tid] = inv;
        g_invl[((size_t)(b * CH + h)) * CS + r0 + tid] = inv;
    }
    __syncthreads();

    {
        int r = wm*16 + crow;
        float inv0 = sInv[r], inv1 = sInv[r + 8];
        size_t ob0 = ((size_t)(b * CS + r0 + r) * CH + h) * CD;
        size_t ob1 = ((size_t)(b * CS + r0 + r + 8) * CH + h) * CD;
#pragma unroll
        for (int nt = 0; nt < 16; nt++) {
            int d = wn*128 + nt*8 + ccol;
            *(float2*)&g_ctx[ob0 + d] = make_float2(acc_o[nt][0]*inv0, acc_o[nt][1]*inv0);
            *(float2*)&g_ctx[ob1 + d] = make_float2(acc_o[nt][2]*inv1, acc_o[nt][3]*inv1);
        }
    }
}

// ---------------- normalize attn rows by 1/l --------------------------------
__global__ void attn_scale_kernel(float* __restrict__ attn)
{
    size_t i = (size_t)blockIdx.x * 256 + threadIdx.x;
    float4* a4 = (float4*)attn;
    size_t row = i >> 9;
    float inv = g_invl[row];
    float4 v = a4[i];
    v.x *= inv; v.y *= inv; v.z *= inv; v.w *= inv;
    a4[i] = v;
}

// ---------------- launch ----------------------------------------------------
extern "C" void kernel_launch(void* const* d_in, const int* in_sizes, int n_in,
                              void* d_out, int out_size)
{
    const float* hs   = (const float*)d_in[0];
    const float* mask = (const float*)d_in[1];
    const int*   pos  = (const int*)  d_in[2];
    const float* Wq   = (const float*)d_in[3];
    const float* bq   = (const float*)d_in[4];
    const float* Wk   = (const float*)d_in[5];
    const float* bk   = (const float*)d_in[6];
    const float* Wv   = (const float*)d_in[7];
    const float* bv   = (const float*)d_in[8];
    const float* Wo   = (const float*)d_in[9];
    const float* bo   = (const float*)d_in[10];
    float* out = (float*)d_out;

    float *qkvp, *ctxp, *bqkvp, *attnfb;
    cudaGetSymbolAddress((void**)&qkvp,   g_qkv);
    cudaGetSymbolAddress((void**)&ctxp,   g_ctx);
    cudaGetSymbolAddress((void**)&bqkvp,  g_bqkv);
    cudaGetSymbolAddress((void**)&attnfb, g_attn_fb);

    __nv_bfloat16 *hsh, *hsl, *wqkvh, *wqkvl, *woh, *wol, *cxh, *cxl, *kbh, *kbl;
    cudaGetSymbolAddress((void**)&hsh,   g_hs_h);   cudaGetSymbolAddress((void**)&hsl,   g_hs_l);
    cudaGetSymbolAddress((void**)&wqkvh, g_wqkv_h); cudaGetSymbolAddress((void**)&wqkvl, g_wqkv_l);
    cudaGetSymbolAddress((void**)&woh,   g_wo_h);   cudaGetSymbolAddress((void**)&wol,   g_wo_l);
    cudaGetSymbolAddress((void**)&cxh,   g_ctx_h);  cudaGetSymbolAddress((void**)&cxl,   g_ctx_l);
    cudaGetSymbolAddress((void**)&kbh,   g_kh);     cudaGetSymbolAddress((void**)&kbl,   g_kl);

    const size_t out_elems  = (size_t)CM * CHID;
    const size_t attn_elems = (size_t)CB * CH * CS * CS;
    float* attn = ((size_t)out_size >= out_elems + attn_elems)
                  ? (out + out_elems) : attnfb;

    // fused bias
    cudaMemcpyAsync(bqkvp,             bq, CHID * sizeof(float), cudaMemcpyDeviceToDevice);
    cudaMemcpyAsync(bqkvp + CHID,      bk, CD   * sizeof(float), cudaMemcpyDeviceToDevice);
    cudaMemcpyAsync(bqkvp + CHID + CD, bv, CD   * sizeof(float), cudaMemcpyDeviceToDevice);

    // splits: hs, stacked Wqkv, Wo
    {
        int n4;
        n4 = (int)((size_t)CM * CHID / 4);
        split_kernel<<<(n4 + 255)/256, 256>>>(hs, hsh, hsl, n4);
        n4 = (int)((size_t)CHID * CHID / 4);
        split_kernel<<<(n4 + 255)/256, 256>>>(Wq, wqkvh, wqkvl, n4);
        split_kernel<<<(n4 + 255)/256, 256>>>(Wo, woh, wol, n4);
        n4 = (int)((size_t)CD * CHID / 4);
        split_kernel<<<(n4 + 255)/256, 256>>>(
            Wk, wqkvh + (size_t)CHID * CHID, wqkvl + (size_t)CHID * CHID, n4);
        split_kernel<<<(n4 + 255)/256, 256>>>(
            Wv, wqkvh + (size_t)(CHID + CD) * CHID, wqkvl + (size_t)(CHID + CD) * CHID, n4);
    }

    // fused QKV projection (single GEMM, N = 2560)
    cudaFuncSetAttribute(gemm_bf16x3, cudaFuncAttributeMaxDynamicSharedMemorySize, GP_SMEM);
    gemm_bf16x3<<<dim3(NQKV/128, CM/128), 256, GP_SMEM>>>(
        hsh, hsl, wqkvh, wqkvl, bqkvp, qkvp, CM, NQKV, CHID);

    // RoPE (on fused buffer)
    {
        int total = CB * CS * (CH + 1) * CHALF;
        rope_kernel<<<(total + 255) / 256, 256>>>(pos);
    }

    // strided splits: q (cols 0..2047), k (cols 2048..2303), v transpose
    {
        int n = CM * (CHID / 4);
        split_strided_kernel<<<(n + 255)/256, 256>>>(qkvp, hsh, hsl, CM, NQKV, 0, CHID);
        n = CM * (CD / 4);
        split_strided_kernel<<<(n + 255)/256, 256>>>(qkvp, kbh, kbl, CM, NQKV, CHID, CD);
        vsplitT_kernel<<<dim3(CS/32, CD/32, CB), 256>>>();
    }

    // fused attention (bf16 3-pass QK and PV)
    cudaFuncSetAttribute(attn_mma_kernel,
                         cudaFuncAttributeMaxDynamicSharedMemorySize, ATTN2_SMEM);
    attn_mma_kernel<<<dim3(CS/BQ, CH, CB), 256, ATTN2_SMEM>>>(mask, attn);

    // normalize attn output
    attn_scale_kernel<<<(int)(attn_elems / 4 / 256), 256>>>(attn);

    // split context, output projection
    {
        int n4 = (int)((size_t)CM * CHID / 4);
        split_kernel<<<(n4 + 255)/256, 256>>>(ctxp, cxh, cxl, n4);
    }
    gemm_bf16x3<<<dim3(CHID/128, CM/128), 256, GP_SMEM>>>(
        cxh, cxl, woh, wol, bo, out, CM, CHID, CHID);
}